// round 6
// baseline (speedup 1.0000x reference)
#include <cuda_runtime.h>

#define NGROUPS 8
#define THREADS 256
#define ROWS_TILE 512                    // rows per block-tile (64B each)
#define TILE_F4 (ROWS_TILE * 4)          // 2048 float4 per tile
#define NBLOCKS 1024
#define MAX_BLOCKS 2048

// Scratch (no allocations allowed). g_part fully overwritten each run;
// g_counter reset to 0 by the last block (deterministic across replays).
__device__ float    g_part[MAX_BLOCKS * 2 * NGROUPS];
__device__ unsigned g_counter = 0;

__device__ __forceinline__ void block_reduce_16(float* s, float* c,
                                                float* red /* [THREADS/32][16] */) {
#pragma unroll
    for (int j = 0; j < NGROUPS; j++) {
#pragma unroll
        for (int o = 16; o > 0; o >>= 1) {
            s[j] += __shfl_down_sync(0xffffffffu, s[j], o);
            c[j] += __shfl_down_sync(0xffffffffu, c[j], o);
        }
    }
    int lane = threadIdx.x & 31;
    int warp = threadIdx.x >> 5;
    if (lane == 0) {
#pragma unroll
        for (int j = 0; j < NGROUPS; j++) {
            red[warp * 16 + j]           = s[j];
            red[warp * 16 + NGROUPS + j] = c[j];
        }
    }
    __syncthreads();
    if (threadIdx.x < 2 * NGROUPS) {
        float t = 0.0f;
#pragma unroll
        for (int w = 0; w < THREADS / 32; w++) t += red[w * 16 + threadIdx.x];
        red[threadIdx.x] = t;   // result lives in red[0..15]
    }
    __syncthreads();
}

__global__ __launch_bounds__(THREADS) void fused_kernel(
    const float* __restrict__ in, const int* __restrict__ tgt,
    const int* __restrict__ grp, float* __restrict__ out, int n)
{
    __shared__ float s_in[ROWS_TILE * 16];     // 32 KB: staged input tile
    __shared__ int   s_tgt[ROWS_TILE];         // 2 KB
    __shared__ int   s_grp[ROWS_TILE];         // 2 KB
    __shared__ float red[(THREADS / 32) * 16];
    __shared__ bool  is_last;

    float s[NGROUPS], c[NGROUPS];
#pragma unroll
    for (int j = 0; j < NGROUPS; j++) { s[j] = 0.0f; c[j] = 0.0f; }

    int ntiles = (n + ROWS_TILE - 1) / ROWS_TILE;
    int tid = threadIdx.x;

    for (int tile = blockIdx.x; tile < ntiles; tile += gridDim.x) {
        int base = tile * ROWS_TILE;

        // ---- Phase 1: STREAM the input tile, fully coalesced (LDG.128),
        // sequential DRAM pattern => near-peak HBM efficiency. The random
        // select moves to smem where it's cheap.
        if (base + ROWS_TILE <= n) {
            const float4* in4 = (const float4*)(in + ((size_t)base << 4));
#pragma unroll
            for (int j = 0; j < TILE_F4 / THREADS; j++) {      // 8 LDG.128
                int idx = tid + j * THREADS;
                ((float4*)s_in)[idx] = __ldcs(in4 + idx);
            }
#pragma unroll
            for (int k = 0; k < ROWS_TILE / THREADS; k++) {    // 2 each
                int m = tid + k * THREADS;
                s_tgt[m] = __ldcs(tgt + base + m);
                s_grp[m] = __ldcs(grp + base + m);
            }
        } else {
            // tail tile: guard everything
            for (int idx = tid; idx < TILE_F4; idx += THREADS) {
                int row = idx >> 2;
                float4 z = make_float4(0.f, 0.f, 0.f, 0.f);
                ((float4*)s_in)[idx] = (base + row < n)
                    ? ((const float4*)(in + ((size_t)base << 4)))[idx] : z;
            }
            for (int m = tid; m < ROWS_TILE; m += THREADS) {
                bool ok = (base + m < n);
                s_tgt[m] = ok ? tgt[base + m] : 0;
                s_grp[m] = ok ? grp[base + m] : -1;
            }
        }
        __syncthreads();

        // ---- Phase 2: LDS gather + per-group accumulation (once per row)
#pragma unroll
        for (int k = 0; k < ROWS_TILE / THREADS; k++) {
            int m = tid + k * THREADS;
            int t = s_tgt[m];
            int g = s_grp[m];
            float v = s_in[(m << 4) + t];
            float e = fabsf(1.0f - v);
#pragma unroll
            for (int j = 0; j < NGROUPS; j++) {
                bool hit = (g == j);
                s[j] += hit ? e : 0.0f;
                c[j] += hit ? 1.0f : 0.0f;      // exact in f32 (< 2^24)
            }
        }
        __syncthreads();   // protect smem before next tile overwrites
    }

    block_reduce_16(s, c, red);

    if (threadIdx.x < 2 * NGROUPS)
        g_part[blockIdx.x * 2 * NGROUPS + threadIdx.x] = red[threadIdx.x];
    __syncthreads();

    if (threadIdx.x == 0) {
        __threadfence();
        unsigned v = atomicAdd(&g_counter, 1u);
        is_last = (v == gridDim.x - 1);
    }
    __syncthreads();
    if (!is_last) return;

    // Final reduction over per-block partials (L2-hot)
    float fs[NGROUPS], fc[NGROUPS];
#pragma unroll
    for (int j = 0; j < NGROUPS; j++) { fs[j] = 0.0f; fc[j] = 0.0f; }
    for (int b = threadIdx.x; b < gridDim.x; b += THREADS) {
#pragma unroll
        for (int j = 0; j < NGROUPS; j++) {
            fs[j] += g_part[b * 2 * NGROUPS + j];
            fc[j] += g_part[b * 2 * NGROUPS + NGROUPS + j];
        }
    }
    __syncthreads();
    block_reduce_16(fs, fc, red);

    if (threadIdx.x == 0) {
        float msum = 0.0f;
#pragma unroll
        for (int j = 0; j < NGROUPS; j++) {
            float cnt = red[NGROUPS + j];
            msum += (cnt > 0.0f) ? (red[j] / cnt) : 0.0f;
        }
        out[0] = fabsf(0.5f - msum * (1.0f / NGROUPS));
        g_counter = 0;   // reset for next graph replay
    }
}

extern "C" void kernel_launch(void* const* d_in, const int* in_sizes, int n_in,
                              void* d_out, int out_size) {
    const float* in  = (const float*)d_in[0];
    const int*   tgt = (const int*)d_in[1];
    const int*   grp = (const int*)d_in[2];
    float*       out = (float*)d_out;
    int n = in_sizes[1];  // N rows

    int ntiles = (n + ROWS_TILE - 1) / ROWS_TILE;
    int blocks = ntiles < NBLOCKS ? ntiles : NBLOCKS;
    if (blocks > MAX_BLOCKS) blocks = MAX_BLOCKS;
    if (blocks < 1) blocks = 1;
    fused_kernel<<<blocks, THREADS>>>(in, tgt, grp, out, n);
}

// round 7
// speedup vs baseline: 1.1355x; 1.1355x over previous
#include <cuda_runtime.h>

#define NGROUPS 8
#define THREADS 256
#define NBLOCKS 740                   // 5 CTAs/SM * 148 SMs (persistent)
#define MAX_BLOCKS 2048

// Scratch (no allocations allowed). g_part fully overwritten each run;
// g_counter reset to 0 by the last block (deterministic across replays).
__device__ float    g_part[MAX_BLOCKS * 2 * NGROUPS];
__device__ unsigned g_counter = 0;

__device__ __forceinline__ void block_reduce_16(float* s, float* c,
                                                float* red /* [THREADS/32][16] */) {
#pragma unroll
    for (int j = 0; j < NGROUPS; j++) {
#pragma unroll
        for (int o = 16; o > 0; o >>= 1) {
            s[j] += __shfl_down_sync(0xffffffffu, s[j], o);
            c[j] += __shfl_down_sync(0xffffffffu, c[j], o);
        }
    }
    int lane = threadIdx.x & 31;
    int warp = threadIdx.x >> 5;
    if (lane == 0) {
#pragma unroll
        for (int j = 0; j < NGROUPS; j++) {
            red[warp * 16 + j]           = s[j];
            red[warp * 16 + NGROUPS + j] = c[j];
        }
    }
    __syncthreads();
    if (threadIdx.x < 2 * NGROUPS) {
        float t = 0.0f;
#pragma unroll
        for (int w = 0; w < THREADS / 32; w++) t += red[w * 16 + threadIdx.x];
        red[threadIdx.x] = t;   // result lives in red[0..15]
    }
    __syncthreads();
}

__global__ __launch_bounds__(THREADS) void fused_kernel(
    const float* __restrict__ in, const int* __restrict__ tgt,
    const int* __restrict__ grp, float* __restrict__ out, int n)
{
    __shared__ float red[(THREADS / 32) * 16];
    __shared__ bool  is_last;

    float s[NGROUPS], c[NGROUPS];
#pragma unroll
    for (int j = 0; j < NGROUPS; j++) { s[j] = 0.0f; c[j] = 0.0f; }

    int stride = gridDim.x * blockDim.x;
    int i0 = blockIdx.x * blockDim.x + threadIdx.x;

    // Whole-row streaming: every load address depends only on i (NO chained
    // gather). A warp's 4 row-quad LDG.128s cover 2048 contiguous bytes =>
    // fully sequential DRAM pattern. Select 1-of-16 in registers afterward.
#pragma unroll 2
    for (int i = i0; i < n; i += stride) {
        const float4* row = (const float4*)(in + ((size_t)i << 4));
        float4 r0 = __ldcs(row + 0);
        float4 r1 = __ldcs(row + 1);
        float4 r2 = __ldcs(row + 2);
        float4 r3 = __ldcs(row + 3);
        int t = __ldcs(tgt + i);
        int g = __ldcs(grp + i);

        // 16 -> 1 select tree (15 SELs)
        int q  = t >> 2;
        int lo = t & 3;
        float4 X = (q & 2) ? ((q & 1) ? r3 : r2) : ((q & 1) ? r1 : r0);
        float  v = (lo & 2) ? ((lo & 1) ? X.w : X.z)
                            : ((lo & 1) ? X.y : X.x);

        float e = fabsf(1.0f - v);
#pragma unroll
        for (int j = 0; j < NGROUPS; j++) {
            bool hit = (g == j);
            s[j] += hit ? e : 0.0f;
            c[j] += hit ? 1.0f : 0.0f;     // exact in f32 (< 2^24)
        }
    }

    block_reduce_16(s, c, red);

    if (threadIdx.x < 2 * NGROUPS)
        g_part[blockIdx.x * 2 * NGROUPS + threadIdx.x] = red[threadIdx.x];
    __syncthreads();

    if (threadIdx.x == 0) {
        __threadfence();
        unsigned v = atomicAdd(&g_counter, 1u);
        is_last = (v == gridDim.x - 1);
    }
    __syncthreads();
    if (!is_last) return;

    // Final reduction over per-block partials (L2-hot)
    float fs[NGROUPS], fc[NGROUPS];
#pragma unroll
    for (int j = 0; j < NGROUPS; j++) { fs[j] = 0.0f; fc[j] = 0.0f; }
    for (int b = threadIdx.x; b < gridDim.x; b += THREADS) {
#pragma unroll
        for (int j = 0; j < NGROUPS; j++) {
            fs[j] += g_part[b * 2 * NGROUPS + j];
            fc[j] += g_part[b * 2 * NGROUPS + NGROUPS + j];
        }
    }
    __syncthreads();
    block_reduce_16(fs, fc, red);

    if (threadIdx.x == 0) {
        float msum = 0.0f;
#pragma unroll
        for (int j = 0; j < NGROUPS; j++) {
            float cnt = red[NGROUPS + j];
            msum += (cnt > 0.0f) ? (red[j] / cnt) : 0.0f;
        }
        out[0] = fabsf(0.5f - msum * (1.0f / NGROUPS));
        g_counter = 0;   // reset for next graph replay
    }
}

extern "C" void kernel_launch(void* const* d_in, const int* in_sizes, int n_in,
                              void* d_out, int out_size) {
    const float* in  = (const float*)d_in[0];
    const int*   tgt = (const int*)d_in[1];
    const int*   grp = (const int*)d_in[2];
    float*       out = (float*)d_out;
    int n = in_sizes[1];  // N rows

    int blocks = NBLOCKS;
    int maxb = (n + THREADS - 1) / THREADS;
    if (blocks > maxb) blocks = maxb;
    if (blocks > MAX_BLOCKS) blocks = MAX_BLOCKS;
    if (blocks < 1) blocks = 1;
    fused_kernel<<<blocks, THREADS>>>(in, tgt, grp, out, n);
}